// round 13
// baseline (speedup 1.0000x reference)
#include <cuda_runtime.h>

// Problem: B=4, C=64, H=128, W=128, N=16, R=4, P=36
#define NPLANES (4*64)
#define PLANE   (128*128)
#define TOTAL   (4*64*128*128)
#define LOG2E   1.4426950408889634f
#define LN2     0.6931471805599453f

typedef unsigned long long ull;

__device__ float g_xT[TOTAL];                   // x transposed (h<->w) per plane
__device__ float g_scr[1024 * 20480 + 256];     // per (seq,l): [dl,du interleaved 128 | B 16 | C 16]
__device__ float g_y[1024 * 128 * 64];          // y[seq][l][c]

__device__ __forceinline__ float ex2f(float v) {
    float r; asm("ex2.approx.ftz.f32 %0, %1;" : "=f"(r) : "f"(v)); return r;
}
__device__ __forceinline__ float lg2f(float v) {
    float r; asm("lg2.approx.f32 %0, %1;" : "=f"(r) : "f"(v)); return r;
}
__device__ __forceinline__ ull pk(float a, float b) {
    ull r; asm("mov.b64 %0, {%1,%2};" : "=l"(r) : "f"(a), "f"(b)); return r;
}
__device__ __forceinline__ float2 upk(ull v) {
    float2 r; asm("mov.b64 {%0,%1}, %2;" : "=f"(r.x), "=f"(r.y) : "l"(v)); return r;
}
__device__ __forceinline__ ull fma2(ull a, ull b, ull c) {
    ull d; asm("fma.rn.f32x2 %0, %1, %2, %3;" : "=l"(d) : "l"(a), "l"(b), "l"(c)); return d;
}
__device__ __forceinline__ ull mul2(ull a, ull b) {
    ull d; asm("mul.rn.f32x2 %0, %1, %2;" : "=l"(d) : "l"(a), "l"(b)); return d;
}

// ---------------- transpose x -> g_xT : float4 both sides, plane-split ----------------
__global__ void transpose_kernel(const float* __restrict__ x, int z0) {
    __shared__ float tile[32][36];
    int plane = z0 + blockIdx.z;
    const float* src = x + plane * PLANE;
    float* dst = g_xT + plane * PLANE;
    int h0 = blockIdx.x * 32, w0 = blockIdx.y * 32;
    int tx = threadIdx.x, ty = threadIdx.y;
    float4 v = *reinterpret_cast<const float4*>(src + (h0 + ty) * 128 + w0 + tx * 4);
    tile[tx * 4 + 0][ty] = v.x;
    tile[tx * 4 + 1][ty] = v.y;
    tile[tx * 4 + 2][ty] = v.z;
    tile[tx * 4 + 3][ty] = v.w;
    __syncthreads();
    float4 o = *reinterpret_cast<const float4*>(&tile[ty][tx * 4]);
    *reinterpret_cast<float4*>(dst + (w0 + ty) * 128 + h0 + tx * 4) = o;
}

// ---------------- proj v4: smem u + register-tiled GEMM, direct B/C stores ----------------
__global__ void __launch_bounds__(256, 4)
proj_kernel(const float* __restrict__ x,
            const float* __restrict__ x_proj_w,
            const float* __restrict__ dt_proj_w,
            const float* __restrict__ dt_proj_b)
{
    __shared__ float sU[64 * 132];    // u tile [c][l] pad 132       (33.8 KB)
    __shared__ float sW[64 * 40];     // x_proj_w [c][p] c-major     (10.2 KB)
    __shared__ float sdt[128 * 4];    // dt_raw [l][4]               ( 2.0 KB)
    __shared__ float sdtw[256];
    __shared__ float sdtb[64];
    const int tid = threadIdx.x;
    const int seq = blockIdx.x;
    const int dir = seq >> 9, sq = seq & 511, b = sq >> 7, row = sq & 127;
    const float* in = dir ? g_xT : x;
    const int base = (b * 64 * 128 + row) * 128;
    float* sbase = g_scr + (size_t)seq * 20480;

    for (int idx = tid; idx < 36 * 64; idx += 256) {
        int p = idx >> 6, c = idx & 63;
        sW[c * 40 + p] = x_proj_w[idx];
    }
    sdtw[tid] = dt_proj_w[tid];
    if (tid < 64) sdtb[tid] = dt_proj_b[tid];
    // u tile: [64 c][128 l], coalesced float4
#pragma unroll
    for (int k = 0; k < 8; k++) {
        int idx = k * 256 + tid;
        int c = idx >> 5, l4 = (idx & 31) * 4;
        *reinterpret_cast<float4*>(&sU[c * 132 + l4]) =
            *reinterpret_cast<const float4*>(in + base + c * 16384 + l4);
    }
    __syncthreads();

    // ---- GEMM: 4l x 4p register tiles, f32x2 over l-pairs; 288 tiles ----
    for (int t = tid; t < 288; t += 256) {
        const int lg = t / 9, pg = t % 9;
        const int l0 = lg * 4, p0 = pg * 4;
        ull A01[4], A23[4];
#pragma unroll
        for (int j = 0; j < 4; j++) { A01[j] = 0ull; A23[j] = 0ull; }
#pragma unroll 4
        for (int c = 0; c < 64; c++) {
            float4 uv = *reinterpret_cast<const float4*>(&sU[c * 132 + l0]);
            float4 wv = *reinterpret_cast<const float4*>(&sW[c * 40 + p0]);
            ull u01 = pk(uv.x, uv.y);
            ull u23 = pk(uv.z, uv.w);
            float ww[4] = {wv.x, wv.y, wv.z, wv.w};
#pragma unroll
            for (int j = 0; j < 4; j++) {
                ull W2 = pk(ww[j], ww[j]);
                A01[j] = fma2(u01, W2, A01[j]);
                A23[j] = fma2(u23, W2, A23[j]);
            }
        }
        float a[4][4];
#pragma unroll
        for (int j = 0; j < 4; j++) {
            float2 lo = upk(A01[j]);
            float2 hi = upk(A23[j]);
            a[0][j] = lo.x; a[1][j] = lo.y; a[2][j] = hi.x; a[3][j] = hi.y;
        }
        if (pg == 0) {
#pragma unroll
            for (int i = 0; i < 4; i++)
                *reinterpret_cast<float4*>(&sdt[(l0 + i) * 4]) =
                    make_float4(a[i][0], a[i][1], a[i][2], a[i][3]);
        } else {
            // B: p 4..19 -> srow[128 + p-4]; C: p 20..35 -> srow[144 + p-20]
            const int off = (pg < 5) ? (128 + (pg - 1) * 4) : (144 + (pg - 5) * 4);
#pragma unroll
            for (int i = 0; i < 4; i++)
                *reinterpret_cast<float4*>(&sbase[(l0 + i) * 160 + off]) =
                    make_float4(a[i][0], a[i][1], a[i][2], a[i][3]);
        }
    }
    __syncthreads();

    // ---- phase 2: softplus for own 32 channels, u from smem ----
    const int l  = tid & 127;
    const int ph = tid >> 7;
    float* srow = sbase + l * 160;
    float4 dt4 = *reinterpret_cast<const float4*>(&sdt[l * 4]);
    const float d0 = dt4.x, d1 = dt4.y, d2 = dt4.z, d3 = dt4.w;

#pragma unroll
    for (int k = 0; k < 32; k += 2) {
        float spv[2], uu[2];
#pragma unroll
        for (int q = 0; q < 2; q++) {
            int dd = ph * 32 + k + q;
            float4 w4 = *reinterpret_cast<const float4*>(&sdtw[dd * 4]);  // broadcast
            float raw = sdtb[dd];
            raw = fmaf(d0, w4.x, raw);
            raw = fmaf(d1, w4.y, raw);
            raw = fmaf(d2, w4.z, raw);
            raw = fmaf(d3, w4.w, raw);
            float e = ex2f(raw * LOG2E);
            spv[q] = (raw > 20.0f) ? raw : lg2f(1.0f + e) * LN2;
            uu[q]  = sU[dd * 132 + l];     // stride-1 over lanes
        }
        *reinterpret_cast<float4*>(&srow[ph * 64 + 2 * k]) =
            make_float4(spv[0], spv[0] * uu[0], spv[1], spv[1] * uu[1]);
    }
}

// ---------------- selective scan: zero smem, 8 CTAs/SM (single wave), f32x2 math ----------------
__global__ void __launch_bounds__(128, 8)
scan_kernel(const float* __restrict__ A_log)
{
    const int tid = threadIdx.x;
    const int seq = blockIdx.x;
    const int d = tid >> 1, half = tid & 1, n0 = half * 8;
    ull A2[4];
#pragma unroll
    for (int j = 0; j < 4; j++) {
        float g0 = -__expf(__ldg(&A_log[d * 16 + n0 + 2 * j + 0])) * LOG2E;
        float g1 = -__expf(__ldg(&A_log[d * 16 + n0 + 2 * j + 1])) * LOG2E;
        A2[j] = pk(g0, g1);
    }

    const float* p = g_scr + (size_t)seq * 20480;
    float* yout = g_y + (size_t)seq * 8192;

    ull h0 = 0ull, h1 = 0ull, h2 = 0ull, h3 = 0ull;

#pragma unroll 2
    for (int l = 0; l < 128; l++) {
        const float* pr = p + l * 160;
        float2 dldu   = __ldg(reinterpret_cast<const float2*>(&pr[2 * d]));
        ulonglong2 Ba = __ldg(reinterpret_cast<const ulonglong2*>(&pr[128 + n0]));
        ulonglong2 Bb = __ldg(reinterpret_cast<const ulonglong2*>(&pr[132 + n0]));
        ulonglong2 Ca = __ldg(reinterpret_cast<const ulonglong2*>(&pr[144 + n0]));
        ulonglong2 Cb = __ldg(reinterpret_cast<const ulonglong2*>(&pr[148 + n0]));

        ull DL2 = pk(dldu.x, dldu.x);
        ull DU2 = pk(dldu.y, dldu.y);
        float2 g0 = upk(mul2(DL2, A2[0]));
        float2 g1 = upk(mul2(DL2, A2[1]));
        float2 g2 = upk(mul2(DL2, A2[2]));
        float2 g3 = upk(mul2(DL2, A2[3]));
        h0 = fma2(pk(ex2f(g0.x), ex2f(g0.y)), h0, mul2(DU2, Ba.x));
        h1 = fma2(pk(ex2f(g1.x), ex2f(g1.y)), h1, mul2(DU2, Ba.y));
        h2 = fma2(pk(ex2f(g2.x), ex2f(g2.y)), h2, mul2(DU2, Bb.x));
        h3 = fma2(pk(ex2f(g3.x), ex2f(g3.y)), h3, mul2(DU2, Bb.y));
        ull T0 = mul2(h0, Ca.x);
        ull T1 = mul2(h1, Ca.y);
        T0 = fma2(h2, Cb.x, T0);
        T1 = fma2(h3, Cb.y, T1);
        float2 ta = upk(T0);
        float2 tb = upk(T1);
        float t = (ta.x + ta.y) + (tb.x + tb.y);
        t += __shfl_xor_sync(0xffffffffu, t, 1);
        if (half == 0) yout[l * 64 + d] = t;
    }
}

// ---------------- combine: out = yh + yv + 2*x*D ----------------
__global__ void __launch_bounds__(256)
combine_kernel(const float* __restrict__ x,
               const float* __restrict__ Dvec,
               float* __restrict__ out)
{
    __shared__ float th[128 * 37];
    __shared__ float tv[128 * 37];
    const int tid = threadIdx.x;
    const int bh = blockIdx.x >> 1;
    const int c0 = (blockIdx.x & 1) * 32;
    const int b = bh >> 7, h = bh & 127;
    const int seq_h = b * 128 + h;

#pragma unroll
    for (int r = 0; r < 4; r++) {
        int idx = r * 256 + tid;            // 0..1023
        int w = idx >> 3, cc = (idx & 7) * 4;
        float4 vh = *reinterpret_cast<const float4*>(&g_y[(size_t)seq_h * 8192 + w * 64 + c0 + cc]);
        th[w * 37 + cc + 0] = vh.x;
        th[w * 37 + cc + 1] = vh.y;
        th[w * 37 + cc + 2] = vh.z;
        th[w * 37 + cc + 3] = vh.w;
        int seq_v = 512 + b * 128 + w;
        float4 vv = *reinterpret_cast<const float4*>(&g_y[(size_t)seq_v * 8192 + h * 64 + c0 + cc]);
        tv[w * 37 + cc + 0] = vv.x;
        tv[w * 37 + cc + 1] = vv.y;
        tv[w * 37 + cc + 2] = vv.z;
        tv[w * 37 + cc + 3] = vv.w;
    }
    __syncthreads();

    const float* xb = x + b * 1048576 + h * 128;
    float* ob = out + b * 1048576 + h * 128;
#pragma unroll
    for (int r = 0; r < 16; r++) {
        int idx = r * 256 + tid;            // 0..4095
        int c = idx >> 7, w = idx & 127;
        int cg = c0 + c;
        float xv = xb[cg * 16384 + w];
        float val = th[w * 37 + c] + tv[w * 37 + c] + 2.0f * xv * __ldg(&Dvec[cg]);
        ob[cg * 16384 + w] = val;
    }
}

extern "C" void kernel_launch(void* const* d_in, const int* in_sizes, int n_in,
                              void* d_out, int out_size) {
    const float* x     = (const float*)d_in[0];
    const float* A_log = (const float*)d_in[1];
    const float* Dv    = (const float*)d_in[2];
    const float* xpw   = (const float*)d_in[3];
    const float* dtw   = (const float*)d_in[4];
    const float* dtb   = (const float*)d_in[5];
    float* out = (float*)d_out;

    dim3 tb(8, 32);
    dim3 tgA(4, 4, 86), tgB(4, 4, 85);
    // Order: T1(0), T2(1), T3(2), P(3 <- profiled), S(4), C(5)
    transpose_kernel<<<tgA, tb>>>(x, 0);
    transpose_kernel<<<tgB, tb>>>(x, 86);
    transpose_kernel<<<tgB, tb>>>(x, 171);
    proj_kernel<<<1024, 256>>>(x, xpw, dtw, dtb);
    scan_kernel<<<1024, 128>>>(A_log);
    combine_kernel<<<1024, 256>>>(x, Dv, out);
}

// round 16
// speedup vs baseline: 1.0801x; 1.0801x over previous
#include <cuda_runtime.h>

// Problem: B=4, C=64, H=128, W=128, N=16, R=4, P=36
#define NPLANES (4*64)
#define PLANE   (128*128)
#define TOTAL   (4*64*128*128)
#define LOG2E   1.4426950408889634f
#define LN2     0.6931471805599453f

typedef unsigned long long ull;

__device__ float g_xT[TOTAL];                   // x transposed (h<->w) per plane
__device__ float g_scr[1024 * 20480 + 256];     // per (seq,l): [dl,du interleaved 128 | B 16 | C 16]
__device__ float g_y[1024 * 128 * 64];          // y[seq][l][c]

__device__ __forceinline__ float ex2f(float v) {
    float r; asm("ex2.approx.ftz.f32 %0, %1;" : "=f"(r) : "f"(v)); return r;
}
__device__ __forceinline__ float lg2f(float v) {
    float r; asm("lg2.approx.f32 %0, %1;" : "=f"(r) : "f"(v)); return r;
}
__device__ __forceinline__ ull pk(float a, float b) {
    ull r; asm("mov.b64 %0, {%1,%2};" : "=l"(r) : "f"(a), "f"(b)); return r;
}
__device__ __forceinline__ float2 upk(ull v) {
    float2 r; asm("mov.b64 {%0,%1}, %2;" : "=f"(r.x), "=f"(r.y) : "l"(v)); return r;
}
__device__ __forceinline__ ull fma2(ull a, ull b, ull c) {
    ull d; asm("fma.rn.f32x2 %0, %1, %2, %3;" : "=l"(d) : "l"(a), "l"(b), "l"(c)); return d;
}
__device__ __forceinline__ ull mul2(ull a, ull b) {
    ull d; asm("mul.rn.f32x2 %0, %1, %2;" : "=l"(d) : "l"(a), "l"(b)); return d;
}

// ---- proj smem layout (floats) ----
#define PR_U    0                    // u [64][132]
#define PR_W    (PR_U + 64*132)      // x_proj_w [64][36] c-major (stride 36, 16B-aligned rows)
#define PR_P    (PR_W + 64*36)       // B/C staging [128][36]
#define PR_DT   (PR_P + 128*36)      // dt_raw [128][4]
#define PR_DTW  (PR_DT + 128*4)      // dt_proj_w [256]
#define PR_DTB  (PR_DTW + 256)       // dt_proj_b [64]
#define PR_FLOATS (PR_DTB + 64)      // 16192 floats = 64768 B
#define PR_BYTES  (PR_FLOATS * 4)

// ---------------- transpose x -> g_xT : float4 both sides, plane-split ----------------
__global__ void transpose_kernel(const float* __restrict__ x, int z0) {
    __shared__ float tile[32][36];
    int plane = z0 + blockIdx.z;
    const float* src = x + plane * PLANE;
    float* dst = g_xT + plane * PLANE;
    int h0 = blockIdx.x * 32, w0 = blockIdx.y * 32;
    int tx = threadIdx.x, ty = threadIdx.y;
    float4 v = *reinterpret_cast<const float4*>(src + (h0 + ty) * 128 + w0 + tx * 4);
    tile[tx * 4 + 0][ty] = v.x;
    tile[tx * 4 + 1][ty] = v.y;
    tile[tx * 4 + 2][ty] = v.z;
    tile[tx * 4 + 3][ty] = v.w;
    __syncthreads();
    float4 o = *reinterpret_cast<const float4*>(&tile[ty][tx * 4]);
    *reinterpret_cast<float4*>(dst + (w0 + ty) * 128 + h0 + tx * 4) = o;
}

// ---------------- proj v5: register-tiled GEMM + fully coalesced scratch writes ----------------
__global__ void __launch_bounds__(256, 3)
proj_kernel(const float* __restrict__ x,
            const float* __restrict__ x_proj_w,
            const float* __restrict__ dt_proj_w,
            const float* __restrict__ dt_proj_b)
{
    extern __shared__ float smx[];
    float* sU   = smx + PR_U;
    float* sW   = smx + PR_W;
    float* sP   = smx + PR_P;
    float* sdt  = smx + PR_DT;
    float* sdtw = smx + PR_DTW;
    float* sdtb = smx + PR_DTB;

    const int tid = threadIdx.x;
    const int seq = blockIdx.x;
    const int dir = seq >> 9, sq = seq & 511, b = sq >> 7, row = sq & 127;
    const float* in = dir ? g_xT : x;
    const int base = (b * 64 * 128 + row) * 128;
    float* sbase = g_scr + (size_t)seq * 20480;

    for (int idx = tid; idx < 36 * 64; idx += 256) {
        int p = idx >> 6, c = idx & 63;
        sW[c * 36 + p] = x_proj_w[idx];
    }
    sdtw[tid] = dt_proj_w[tid];
    if (tid < 64) sdtb[tid] = dt_proj_b[tid];
    // u tile: [64 c][128 l], coalesced float4
#pragma unroll
    for (int k = 0; k < 8; k++) {
        int idx = k * 256 + tid;
        int c = idx >> 5, l4 = (idx & 31) * 4;
        *reinterpret_cast<float4*>(&sU[c * 132 + l4]) =
            *reinterpret_cast<const float4*>(in + base + c * 16384 + l4);
    }
    __syncthreads();

    // ---- GEMM: 4l x 4p register tiles, f32x2 over l-pairs; outputs to smem only ----
    for (int t = tid; t < 288; t += 256) {
        const int lg = t / 9, pg = t % 9;
        const int l0 = lg * 4, p0 = pg * 4;
        ull A01[4], A23[4];
#pragma unroll
        for (int j = 0; j < 4; j++) { A01[j] = 0ull; A23[j] = 0ull; }
#pragma unroll 4
        for (int c = 0; c < 64; c++) {
            float4 uv = *reinterpret_cast<const float4*>(&sU[c * 132 + l0]);
            float4 wv = *reinterpret_cast<const float4*>(&sW[c * 36 + p0]);
            ull u01 = pk(uv.x, uv.y);
            ull u23 = pk(uv.z, uv.w);
            float ww[4] = {wv.x, wv.y, wv.z, wv.w};
#pragma unroll
            for (int j = 0; j < 4; j++) {
                ull W2 = pk(ww[j], ww[j]);
                A01[j] = fma2(u01, W2, A01[j]);
                A23[j] = fma2(u23, W2, A23[j]);
            }
        }
        float a[4][4];
#pragma unroll
        for (int j = 0; j < 4; j++) {
            float2 lo = upk(A01[j]);
            float2 hi = upk(A23[j]);
            a[0][j] = lo.x; a[1][j] = lo.y; a[2][j] = hi.x; a[3][j] = hi.y;
        }
        if (pg == 0) {
#pragma unroll
            for (int i = 0; i < 4; i++)
                *reinterpret_cast<float4*>(&sdt[(l0 + i) * 4]) =
                    make_float4(a[i][0], a[i][1], a[i][2], a[i][3]);
        } else {
            // B (p 4..19) -> sP cols 0..15 ; C (p 20..35) -> sP cols 16..31
            const int col = (pg - 1) * 4;
#pragma unroll
            for (int i = 0; i < 4; i++)
                *reinterpret_cast<float4*>(&sP[(l0 + i) * 36 + col]) =
                    make_float4(a[i][0], a[i][1], a[i][2], a[i][3]);
        }
    }
    __syncthreads();

    // ---- phase 2: warp owns row, lane owns channel pair -> coalesced 512B row stores ----
    {
        const int warp = tid >> 5, lane = tid & 31;
        const int dd0 = 2 * lane, dd1 = 2 * lane + 1;
        float4 w40 = *reinterpret_cast<const float4*>(&sdtw[dd0 * 4]);
        float4 w41 = *reinterpret_cast<const float4*>(&sdtw[dd1 * 4]);
        float b0 = sdtb[dd0], b1 = sdtb[dd1];
#pragma unroll
        for (int r = 0; r < 16; r++) {
            int l = warp * 16 + r;
            float4 dt4 = *reinterpret_cast<const float4*>(&sdt[l * 4]);   // broadcast
            float raw0 = fmaf(dt4.w, w40.w, fmaf(dt4.z, w40.z, fmaf(dt4.y, w40.y, fmaf(dt4.x, w40.x, b0))));
            float raw1 = fmaf(dt4.w, w41.w, fmaf(dt4.z, w41.z, fmaf(dt4.y, w41.y, fmaf(dt4.x, w41.x, b1))));
            float e0 = ex2f(raw0 * LOG2E);
            float e1 = ex2f(raw1 * LOG2E);
            float sp0 = (raw0 > 20.0f) ? raw0 : lg2f(1.0f + e0) * LN2;
            float sp1 = (raw1 > 20.0f) ? raw1 : lg2f(1.0f + e1) * LN2;
            float u0 = sU[dd0 * 132 + l];
            float u1 = sU[dd1 * 132 + l];
            // warp writes contiguous 512B: lane*16B within the row
            *reinterpret_cast<float4*>(&sbase[l * 160 + lane * 4]) =
                make_float4(sp0, sp0 * u0, sp1, sp1 * u1);
        }
        // B/C writeout: 4 rows x 8 float4 lanes per iter -> full 128B chunks
#pragma unroll
        for (int i = 0; i < 4; i++) {
            int l = warp * 16 + i * 4 + (lane >> 3);
            int j = (lane & 7) * 4;
            float4 v = *reinterpret_cast<const float4*>(&sP[l * 36 + j]);
            *reinterpret_cast<float4*>(&sbase[l * 160 + 128 + j]) = v;
        }
    }
}

// ---------------- selective scan: zero smem, 8 CTAs/SM (single wave), f32x2 math ----------------
__global__ void __launch_bounds__(128, 8)
scan_kernel(const float* __restrict__ A_log)
{
    const int tid = threadIdx.x;
    const int seq = blockIdx.x;
    const int d = tid >> 1, half = tid & 1, n0 = half * 8;
    ull A2[4];
#pragma unroll
    for (int j = 0; j < 4; j++) {
        float g0 = -__expf(__ldg(&A_log[d * 16 + n0 + 2 * j + 0])) * LOG2E;
        float g1 = -__expf(__ldg(&A_log[d * 16 + n0 + 2 * j + 1])) * LOG2E;
        A2[j] = pk(g0, g1);
    }

    const float* p = g_scr + (size_t)seq * 20480;
    float* yout = g_y + (size_t)seq * 8192;

    ull h0 = 0ull, h1 = 0ull, h2 = 0ull, h3 = 0ull;

#pragma unroll 2
    for (int l = 0; l < 128; l++) {
        const float* pr = p + l * 160;
        float2 dldu   = __ldg(reinterpret_cast<const float2*>(&pr[2 * d]));
        ulonglong2 Ba = __ldg(reinterpret_cast<const ulonglong2*>(&pr[128 + n0]));
        ulonglong2 Bb = __ldg(reinterpret_cast<const ulonglong2*>(&pr[132 + n0]));
        ulonglong2 Ca = __ldg(reinterpret_cast<const ulonglong2*>(&pr[144 + n0]));
        ulonglong2 Cb = __ldg(reinterpret_cast<const ulonglong2*>(&pr[148 + n0]));

        ull DL2 = pk(dldu.x, dldu.x);
        ull DU2 = pk(dldu.y, dldu.y);
        float2 g0 = upk(mul2(DL2, A2[0]));
        float2 g1 = upk(mul2(DL2, A2[1]));
        float2 g2 = upk(mul2(DL2, A2[2]));
        float2 g3 = upk(mul2(DL2, A2[3]));
        h0 = fma2(pk(ex2f(g0.x), ex2f(g0.y)), h0, mul2(DU2, Ba.x));
        h1 = fma2(pk(ex2f(g1.x), ex2f(g1.y)), h1, mul2(DU2, Ba.y));
        h2 = fma2(pk(ex2f(g2.x), ex2f(g2.y)), h2, mul2(DU2, Bb.x));
        h3 = fma2(pk(ex2f(g3.x), ex2f(g3.y)), h3, mul2(DU2, Bb.y));
        ull T0 = mul2(h0, Ca.x);
        ull T1 = mul2(h1, Ca.y);
        T0 = fma2(h2, Cb.x, T0);
        T1 = fma2(h3, Cb.y, T1);
        float2 ta = upk(T0);
        float2 tb = upk(T1);
        float t = (ta.x + ta.y) + (tb.x + tb.y);
        t += __shfl_xor_sync(0xffffffffu, t, 1);
        if (half == 0) yout[l * 64 + d] = t;
    }
}

// ---------------- combine: out = yh + yv + 2*x*D ----------------
__global__ void __launch_bounds__(256)
combine_kernel(const float* __restrict__ x,
               const float* __restrict__ Dvec,
               float* __restrict__ out)
{
    __shared__ float th[128 * 37];
    __shared__ float tv[128 * 37];
    const int tid = threadIdx.x;
    const int bh = blockIdx.x >> 1;
    const int c0 = (blockIdx.x & 1) * 32;
    const int b = bh >> 7, h = bh & 127;
    const int seq_h = b * 128 + h;

#pragma unroll
    for (int r = 0; r < 4; r++) {
        int idx = r * 256 + tid;            // 0..1023
        int w = idx >> 3, cc = (idx & 7) * 4;
        float4 vh = *reinterpret_cast<const float4*>(&g_y[(size_t)seq_h * 8192 + w * 64 + c0 + cc]);
        th[w * 37 + cc + 0] = vh.x;
        th[w * 37 + cc + 1] = vh.y;
        th[w * 37 + cc + 2] = vh.z;
        th[w * 37 + cc + 3] = vh.w;
        int seq_v = 512 + b * 128 + w;
        float4 vv = *reinterpret_cast<const float4*>(&g_y[(size_t)seq_v * 8192 + h * 64 + c0 + cc]);
        tv[w * 37 + cc + 0] = vv.x;
        tv[w * 37 + cc + 1] = vv.y;
        tv[w * 37 + cc + 2] = vv.z;
        tv[w * 37 + cc + 3] = vv.w;
    }
    __syncthreads();

    const float* xb = x + b * 1048576 + h * 128;
    float* ob = out + b * 1048576 + h * 128;
#pragma unroll
    for (int r = 0; r < 16; r++) {
        int idx = r * 256 + tid;            // 0..4095
        int c = idx >> 7, w = idx & 127;
        int cg = c0 + c;
        float xv = xb[cg * 16384 + w];
        float val = th[w * 37 + c] + tv[w * 37 + c] + 2.0f * xv * __ldg(&Dvec[cg]);
        ob[cg * 16384 + w] = val;
    }
}

extern "C" void kernel_launch(void* const* d_in, const int* in_sizes, int n_in,
                              void* d_out, int out_size) {
    const float* x     = (const float*)d_in[0];
    const float* A_log = (const float*)d_in[1];
    const float* Dv    = (const float*)d_in[2];
    const float* xpw   = (const float*)d_in[3];
    const float* dtw   = (const float*)d_in[4];
    const float* dtb   = (const float*)d_in[5];
    float* out = (float*)d_out;

    cudaFuncSetAttribute(proj_kernel, cudaFuncAttributeMaxDynamicSharedMemorySize, PR_BYTES);

    dim3 tb(8, 32);
    dim3 tgA(4, 4, 86), tgB(4, 4, 85);
    // Order: T1(0), T2(1), T3(2), P(3 <- profiled), S(4), C(5)
    transpose_kernel<<<tgA, tb>>>(x, 0);
    transpose_kernel<<<tgB, tb>>>(x, 86);
    transpose_kernel<<<tgB, tb>>>(x, 171);
    proj_kernel<<<1024, 256, PR_BYTES>>>(x, xpw, dtw, dtb);
    scan_kernel<<<1024, 128>>>(A_log);
    combine_kernel<<<1024, 256>>>(x, Dv, out);
}